// round 14
// baseline (speedup 1.0000x reference)
#include <cuda_runtime.h>
#include <cuda_bf16.h>
#include <cuda_fp16.h>
#include <math.h>

// Problem constants (fixed shapes per reference)
#define NN 50000
#define EE 800000
#define GG 64
#define FIN 64
#define HH 64
#define RR 3
#define CC 10
#define YW 832   // packed GEMM width
#define YH 640   // half-precision edge-accessed width (cols 192..832)
#define NK (NN * RR)                            // 150000 (dst,type) bins
#define SCAN_B 1024
#define SCAN_NB ((NK + SCAN_B - 1) / SCAN_B)    // 147

// Column layout in Wcat (GEMM output):
//  [0,128)   fs   = x @ skip_film_W + skip_film_b     -> d_Y192 fp32
//  [128,192) skip = x @ skip_W                        -> d_Y192 fp32
//  [192,384) xr   : r*64 + h  = x @ film_lin_W[r]     -> d_Yh fp16 (col j-192)
//  [384,768) fm   : r*128 + c (beta c<64, gamma c>=64)-> d_Yh fp16
//  [768,832) xp   = x @ gat_W                         -> d_Yh fp16 (cols 576..640)

// ---------------- scratch (device globals; no allocation allowed) -------------
__device__ float    d_Y192[(size_t)NN * 192];
__device__ __half   d_Yh[(size_t)NN * YH];
__device__ float    d_Wcat[64 * YW];
__device__ float    d_bcat[YW];
__device__ float    d_as[NN];
__device__ float    d_ad[NN];
__device__ int      d_hist[NK];
__device__ int      d_segoff[NK + 1];
__device__ int      d_cursor[NK];
__device__ int      d_blksum[SCAN_NB];
__device__ int      d_blkoff[SCAN_NB];
__device__ int      d_sorted[EE];          // src index (sorted by dst*3+type)
__device__ int      d_poolmax[GG * 128];   // float bits, values >= 0
__device__ float    d_poolsum[GG * 128];
__device__ int      d_gcnt[GG];

// ---------------- streams/events for fork-join inside graph capture -----------
static cudaStream_t g_s2;
static cudaEvent_t  g_evFork, g_evJoin;
struct _StreamInit {
    _StreamInit() {
        cudaStreamCreateWithFlags(&g_s2, cudaStreamNonBlocking);
        cudaEventCreateWithFlags(&g_evFork, cudaEventDisableTiming);
        cudaEventCreateWithFlags(&g_evJoin, cudaEventDisableTiming);
    }
};
static _StreamInit g_streamInit;

// ---------------- helpers ----------------
__device__ __forceinline__ float lrelu(float x) { return x > 0.f ? x : 0.2f * x; }
__device__ __forceinline__ float frelu(float x) { return fmaxf(x, 0.f); }
__device__ __forceinline__ unsigned f2tf(float f) {
    unsigned u;
    asm("cvt.rna.tf32.f32 %0, %1;" : "=r"(u) : "f"(f));
    return u;
}
__device__ __forceinline__ void mma_tf32(float* d, const unsigned* a, const unsigned* b) {
    asm volatile(
        "mma.sync.aligned.m16n8k8.row.col.f32.tf32.tf32.f32 "
        "{%0,%1,%2,%3}, {%4,%5,%6,%7}, {%8,%9}, {%0,%1,%2,%3};"
        : "+f"(d[0]), "+f"(d[1]), "+f"(d[2]), "+f"(d[3])
        : "r"(a[0]), "r"(a[1]), "r"(a[2]), "r"(a[3]), "r"(b[0]), "r"(b[1]));
}
__device__ __forceinline__ float2 ldh2(const __half* p) {
    return __half22float2(*(const __half2*)p);
}
__device__ __forceinline__ float4 ldh4(const __half* p) {
    uint2 u = *(const uint2*)p;
    __half2 a = *(__half2*)&u.x, b = *(__half2*)&u.y;
    float2 fa = __half22float2(a), fb = __half22float2(b);
    return make_float4(fa.x, fa.y, fb.x, fb.y);
}

// ---------------- 1. pack weights + biases ----------------
__global__ void pack_kernel(const float* __restrict__ skip_film_W,
                            const float* __restrict__ skip_W,
                            const float* __restrict__ film_lin_W,
                            const float* __restrict__ film_film_W,
                            const float* __restrict__ film_film_b,
                            const float* __restrict__ skip_film_b,
                            const float* __restrict__ gat_W) {
    int stride = blockDim.x * gridDim.x;
    for (int idx = blockIdx.x * blockDim.x + threadIdx.x; idx < 64 * YW; idx += stride) {
        int d = idx / YW, j = idx % YW;
        float v;
        if (j < 128)        v = skip_film_W[d * 128 + j];
        else if (j < 192)   v = skip_W[d * 64 + (j - 128)];
        else if (j < 384) { int r = (j - 192) >> 6, h = (j - 192) & 63;
                            v = film_lin_W[r * 4096 + d * 64 + h]; }
        else if (j < 768) { int r = (j - 384) >> 7, c = (j - 384) & 127;
                            v = film_film_W[r * 8192 + d * 128 + c]; }
        else                v = gat_W[d * 64 + (j - 768)];
        d_Wcat[idx] = v;
    }
    for (int j = blockIdx.x * blockDim.x + threadIdx.x; j < YW; j += stride) {
        float b = 0.f;
        if (j < 128)                 b = skip_film_b[j];
        else if (j >= 384 && j < 768) { int r = (j - 384) >> 7, c = (j - 384) & 127;
                                        b = film_film_b[r * 128 + c]; }
        d_bcat[j] = b;
    }
}

// ---------------- 2. zero scratch ----------------
__global__ void zero_kernel() {
    int stride = blockDim.x * gridDim.x;
    int t = blockIdx.x * blockDim.x + threadIdx.x;
    for (int i = t; i < NK; i += stride) { d_hist[i] = 0; d_cursor[i] = 0; }
    for (int i = t; i < GG * 128; i += stride) { d_poolmax[i] = 0; d_poolsum[i] = 0.f; }
    for (int i = t; i < GG; i += stride)      d_gcnt[i] = 0;
}

// ---------------- 3. tensor-core GEMM (TF32; 3x split only for fp32 cols) -----
__global__ __launch_bounds__(256) void gemm_tc_kernel(const float* __restrict__ A, int n) {
    __shared__ float As[128][68];
    __shared__ float Bs[64][72];
    int row0 = blockIdx.x * 128;
    int col0 = blockIdx.y * 64;
    int tid = threadIdx.x;
    bool is_half = (col0 >= 192);   // fp16-dest cols: single-pass TF32 suffices

    #pragma unroll
    for (int i = 0; i < 8; i++) {
        int e = i * 256 + tid;
        int r = e >> 4;
        int c4 = (e & 15) << 2;
        float4 v = make_float4(0.f, 0.f, 0.f, 0.f);
        if (row0 + r < n) v = *(const float4*)(A + (size_t)(row0 + r) * 64 + c4);
        As[r][c4] = v.x; As[r][c4 + 1] = v.y; As[r][c4 + 2] = v.z; As[r][c4 + 3] = v.w;
    }
    #pragma unroll
    for (int i = 0; i < 4; i++) {
        int e = i * 256 + tid;
        int k = e >> 4;
        int c4 = (e & 15) << 2;
        float4 v = *(const float4*)(d_Wcat + k * YW + col0 + c4);
        Bs[k][c4] = v.x; Bs[k][c4 + 1] = v.y; Bs[k][c4 + 2] = v.z; Bs[k][c4 + 3] = v.w;
    }
    __syncthreads();

    int warp = tid >> 5, lane = tid & 31;
    int wm = (warp >> 1) * 32;
    int wn = (warp & 1) * 32;
    int lr = lane >> 2;
    int lc = lane & 3;

    float acc[2][4][4] = {};
    #pragma unroll
    for (int k0 = 0; k0 < 64; k0 += 8) {
        unsigned abig[2][4], asml[2][4];
        float aval[2][4];
        #pragma unroll
        for (int mi = 0; mi < 2; mi++) {
            int r = wm + mi * 16 + lr;
            aval[mi][0] = As[r][k0 + lc];
            aval[mi][1] = As[r + 8][k0 + lc];
            aval[mi][2] = As[r][k0 + 4 + lc];
            aval[mi][3] = As[r + 8][k0 + 4 + lc];
            #pragma unroll
            for (int q = 0; q < 4; q++) abig[mi][q] = f2tf(aval[mi][q]);
        }
        unsigned bbig[4][2], bsml[4][2];
        float bval[4][2];
        #pragma unroll
        for (int ni = 0; ni < 4; ni++) {
            int c = wn + ni * 8 + lr;
            bval[ni][0] = Bs[k0 + lc][c];
            bval[ni][1] = Bs[k0 + 4 + lc][c];
            bbig[ni][0] = f2tf(bval[ni][0]);
            bbig[ni][1] = f2tf(bval[ni][1]);
        }
        #pragma unroll
        for (int mi = 0; mi < 2; mi++)
            #pragma unroll
            for (int ni = 0; ni < 4; ni++)
                mma_tf32(acc[mi][ni], abig[mi], bbig[ni]);
        if (!is_half) {   // correction passes only for fp32-dest columns
            #pragma unroll
            for (int mi = 0; mi < 2; mi++)
                #pragma unroll
                for (int q = 0; q < 4; q++)
                    asml[mi][q] = f2tf(aval[mi][q] - __uint_as_float(abig[mi][q]));
            #pragma unroll
            for (int ni = 0; ni < 4; ni++) {
                bsml[ni][0] = f2tf(bval[ni][0] - __uint_as_float(bbig[ni][0]));
                bsml[ni][1] = f2tf(bval[ni][1] - __uint_as_float(bbig[ni][1]));
            }
            #pragma unroll
            for (int mi = 0; mi < 2; mi++)
                #pragma unroll
                for (int ni = 0; ni < 4; ni++) {
                    mma_tf32(acc[mi][ni], abig[mi], bsml[ni]);
                    mma_tf32(acc[mi][ni], asml[mi], bbig[ni]);
                }
        }
    }

    #pragma unroll
    for (int mi = 0; mi < 2; mi++) {
        #pragma unroll
        for (int ni = 0; ni < 4; ni++) {
            int c = col0 + wn + ni * 8 + 2 * lc;
            float b0 = d_bcat[c], b1 = d_bcat[c + 1];
            int r0 = row0 + wm + mi * 16 + lr;
            #pragma unroll
            for (int rr = 0; rr < 2; rr++) {
                int r = r0 + rr * 8;
                if (r >= n) continue;
                float v0 = acc[mi][ni][rr * 2] + b0;
                float v1 = acc[mi][ni][rr * 2 + 1] + b1;
                if (is_half) {
                    *(__half2*)(d_Yh + (size_t)r * YH + (c - 192)) = __floats2half2_rn(v0, v1);
                } else {
                    *(float2*)(d_Y192 + (size_t)r * 192 + c) = make_float2(v0, v1);
                }
            }
        }
    }
}

// ---------------- 4. node epilogue: attention dot products --------------------
// 8 lanes per node, 16B loads, width-8 shuffle reduce.
__global__ void node_epi_kernel(int n, const float* __restrict__ att_src,
                                const float* __restrict__ att_dst) {
    int gt = blockIdx.x * blockDim.x + threadIdx.x;
    int node = gt >> 3;
    int sub = gt & 7;
    if (node >= n) return;
    const __half* xph = d_Yh + (size_t)node * YH + 576 + sub * 8;
    float4 a = ldh4(xph);
    float4 b = ldh4(xph + 4);
    int j = sub * 8;
    float ps = a.x * att_src[j]     + a.y * att_src[j + 1]
             + a.z * att_src[j + 2] + a.w * att_src[j + 3]
             + b.x * att_src[j + 4] + b.y * att_src[j + 5]
             + b.z * att_src[j + 6] + b.w * att_src[j + 7];
    float pd = a.x * att_dst[j]     + a.y * att_dst[j + 1]
             + a.z * att_dst[j + 2] + a.w * att_dst[j + 3]
             + b.x * att_dst[j + 4] + b.y * att_dst[j + 5]
             + b.z * att_dst[j + 6] + b.w * att_dst[j + 7];
    #pragma unroll
    for (int off = 4; off > 0; off >>= 1) {
        ps += __shfl_down_sync(0xffffffffu, ps, off, 8);
        pd += __shfl_down_sync(0xffffffffu, pd, off, 8);
    }
    if (sub == 0) { d_as[node] = ps; d_ad[node] = pd; }
}

// ---------------- 5. counting sort of edges by (dst,type) --------------------
__global__ void hist_kernel(int ne, const int* __restrict__ ei,
                            const int* __restrict__ et) {
    int e = blockIdx.x * blockDim.x + threadIdx.x;
    if (e >= ne) return;
    atomicAdd(&d_hist[ei[ne + e] * RR + et[e]], 1);
}

__global__ __launch_bounds__(SCAN_B) void scan_local_kernel() {
    __shared__ int warp_tot[32];
    int b = blockIdx.x, tid = threadIdx.x, lane = tid & 31, wid = tid >> 5;
    int i = b * SCAN_B + tid;
    int v = (i < NK) ? d_hist[i] : 0;
    int x = v;
    #pragma unroll
    for (int o = 1; o < 32; o <<= 1) {
        int y = __shfl_up_sync(0xffffffffu, x, o);
        if (lane >= o) x += y;
    }
    if (lane == 31) warp_tot[wid] = x;
    __syncthreads();
    if (wid == 0) {
        int w = warp_tot[lane];
        #pragma unroll
        for (int o = 1; o < 32; o <<= 1) {
            int y = __shfl_up_sync(0xffffffffu, w, o);
            if (lane >= o) w += y;
        }
        warp_tot[lane] = w;
    }
    __syncthreads();
    int incl = x + (wid > 0 ? warp_tot[wid - 1] : 0);
    if (i < NK) d_segoff[i] = incl - v;
    if (tid == SCAN_B - 1) d_blksum[b] = incl;
}

// scan the SCAN_NB (=147) block sums with one 256-thread block
__global__ void scan_mid_kernel() {
    __shared__ int wt[8];
    int tid = threadIdx.x, lane = tid & 31, wid = tid >> 5;
    int v = (tid < SCAN_NB) ? d_blksum[tid] : 0;
    int x = v;
    #pragma unroll
    for (int o = 1; o < 32; o <<= 1) {
        int y = __shfl_up_sync(0xffffffffu, x, o);
        if (lane >= o) x += y;
    }
    if (lane == 31) wt[wid] = x;
    __syncthreads();
    if (wid == 0) {
        int w = (lane < 8) ? wt[lane] : 0;
        #pragma unroll
        for (int o = 1; o < 8; o <<= 1) {
            int y = __shfl_up_sync(0xffffffffu, w, o);
            if (lane >= o) w += y;
        }
        if (lane < 8) wt[lane] = w;
    }
    __syncthreads();
    int incl = x + (wid > 0 ? wt[wid - 1] : 0);
    if (tid < SCAN_NB) d_blkoff[tid] = incl - v;
    if (tid == 0) d_segoff[NK] = wt[7];
}

__global__ void scan_add_kernel() {
    int i = blockIdx.x * blockDim.x + threadIdx.x;
    if (i < NK) d_segoff[i] += d_blkoff[i >> 10];
}

__global__ void scatter_kernel(int ne, const int* __restrict__ ei,
                               const int* __restrict__ et) {
    int e = blockIdx.x * blockDim.x + threadIdx.x;
    if (e >= ne) return;
    int s = ei[e];
    int k = ei[ne + e] * RR + et[e];
    int pos = d_segoff[k] + atomicAdd(&d_cursor[k], 1);
    d_sorted[pos] = s;
}

// ---------------- 6. aggregation + pooling: one warp per dst ------------------
// Lane-role split: lanes 0-15 own FiLM features 4f..4f+3 (load xr row only),
// lanes 16-31 own GAT features 4q..4q+3 (load xp row only). One 8B load per
// lane per edge -> half the dependent-load chain vs ldh2 x2. Pooling staged in
// smem per block (graph_batch is sorted).
__global__ __launch_bounds__(256) void agg_kernel(int n, const int* __restrict__ gb,
                                                  const float* __restrict__ gat_b) {
    __shared__ int   s_g[8];
    __shared__ int   s_max[128];
    __shared__ float s_sum[128];
    int wslot = threadIdx.x >> 5;
    int l = threadIdx.x & 31;
    int d = blockIdx.x * 8 + wslot;
    bool active = d < n;
    bool fl = l < 16;              // FiLM role
    int f4 = (l & 15) << 2;        // feature base (0..60)

    float p0 = 0.f, p1 = 0.f, p2 = 0.f, p3 = 0.f;   // pooled values out
    int g = -1;

    if (active) {
        const __half* yh_d = d_Yh + (size_t)d * YH;
        float ad_d = d_ad[d];
        float denom = 0.f;
        float a0 = 0.f, a1 = 0.f, a2 = 0.f, a3 = 0.f;   // GAT accum (lanes>=16)
        float m0 = 0.f, m1 = 0.f, m2 = 0.f, m3 = 0.f;   // FiLM total (lanes<16)

        #pragma unroll
        for (int t = 0; t < RR; t++) {
            float4 be = make_float4(0.f, 0.f, 0.f, 0.f);
            float4 ga = make_float4(0.f, 0.f, 0.f, 0.f);
            if (fl) {
                be = ldh4(yh_d + 192 + t * 128 + f4);
                ga = ldh4(yh_d + 192 + t * 128 + 64 + f4);
            }
            int beg = d_segoff[d * RR + t], end = d_segoff[d * RR + t + 1];
            float t0 = 0.f, t1 = 0.f, t2 = 0.f, t3 = 0.f;
            int roff = fl ? (t * 64 + f4) : (576 + f4);
            for (int base = beg; base < end; base += 32) {
                int i = base + l;
                int sk = 0; float ex = 0.f;
                if (i < end) {
                    sk = d_sorted[i];
                    ex = __expf(lrelu(d_as[sk] + ad_d));
                }
                int m = min(32, end - base);
                #pragma unroll 4
                for (int j = 0; j < m; j++) {
                    int sj    = __shfl_sync(0xffffffffu, sk, j);
                    float exj = __shfl_sync(0xffffffffu, ex, j);
                    denom += exj;
                    float4 v = ldh4(d_Yh + (size_t)sj * YH + roff);
                    if (fl) {
                        t0 += frelu(ga.x * v.x + be.x);
                        t1 += frelu(ga.y * v.y + be.y);
                        t2 += frelu(ga.z * v.z + be.z);
                        t3 += frelu(ga.w * v.w + be.w);
                    } else {
                        a0 += exj * v.x; a1 += exj * v.y;
                        a2 += exj * v.z; a3 += exj * v.w;
                    }
                }
            }
            float rc = 1.f / fmaxf((float)(end - beg), 1.f);
            m0 += t0 * rc; m1 += t1 * rc; m2 += t2 * rc; m3 += t3 * rc;
        }

        // GAT self loop (denominator in all lanes; xp term in GAT lanes)
        float ex_self = __expf(lrelu(d_as[d] + ad_d));
        denom += ex_self;
        if (!fl) {
            float4 xpd = ldh4(yh_d + 576 + f4);
            a0 += ex_self * xpd.x; a1 += ex_self * xpd.y;
            a2 += ex_self * xpd.z; a3 += ex_self * xpd.w;
        }
        float rden = 1.f / denom;

        if (fl) {
            const float* yr = d_Y192 + (size_t)d * 192;
            float4 fsb = *(const float4*)(yr + f4);
            float4 fsg = *(const float4*)(yr + 64 + f4);
            float4 skv = *(const float4*)(yr + 128 + f4);
            p0 = frelu(frelu(fsg.x * skv.x + fsb.x) + m0);
            p1 = frelu(frelu(fsg.y * skv.y + fsb.y) + m1);
            p2 = frelu(frelu(fsg.z * skv.z + fsb.z) + m2);
            p3 = frelu(frelu(fsg.w * skv.w + fsb.w) + m3);
        } else {
            p0 = frelu(a0 * rden + gat_b[f4]);
            p1 = frelu(a1 * rden + gat_b[f4 + 1]);
            p2 = frelu(a2 * rden + gat_b[f4 + 2]);
            p3 = frelu(a3 * rden + gat_b[f4 + 3]);
        }

        g = __shfl_sync(0xffffffffu, (l == 0) ? gb[d] : 0, 0);
    }

    int pidx = (fl ? f4 : 64 + f4);   // index within 128-wide feature vector

    if (l == 0) s_g[wslot] = active ? g : -1;
    __syncthreads();
    int g0 = s_g[0];
    bool uni = (g0 >= 0);
    #pragma unroll
    for (int i = 1; i < 8; i++) uni = uni && (s_g[i] == g0);

    if (uni) {
        // block-staged pooling: smem reduce, then 128+128 global atomics per block
        if (threadIdx.x < 128) { s_max[threadIdx.x] = 0; s_sum[threadIdx.x] = 0.f; }
        __syncthreads();
        atomicMax(&s_max[pidx],     __float_as_int(p0));
        atomicMax(&s_max[pidx + 1], __float_as_int(p1));
        atomicMax(&s_max[pidx + 2], __float_as_int(p2));
        atomicMax(&s_max[pidx + 3], __float_as_int(p3));
        atomicAdd(&s_sum[pidx],     p0);
        atomicAdd(&s_sum[pidx + 1], p1);
        atomicAdd(&s_sum[pidx + 2], p2);
        atomicAdd(&s_sum[pidx + 3], p3);
        __syncthreads();
        if (threadIdx.x < 128) {
            atomicMax(&d_poolmax[g0 * 128 + threadIdx.x], s_max[threadIdx.x]);
            atomicAdd(&d_poolsum[g0 * 128 + threadIdx.x], s_sum[threadIdx.x]);
        }
        if (threadIdx.x == 0) atomicAdd(&d_gcnt[g0], 8);
    } else if (active) {
        // fallback: direct global atomics (graph-boundary or tail blocks)
        int pbase = g * 128 + pidx;
        atomicMax(&d_poolmax[pbase],     __float_as_int(p0));
        atomicMax(&d_poolmax[pbase + 1], __float_as_int(p1));
        atomicMax(&d_poolmax[pbase + 2], __float_as_int(p2));
        atomicMax(&d_poolmax[pbase + 3], __float_as_int(p3));
        atomicAdd(&d_poolsum[pbase],     p0);
        atomicAdd(&d_poolsum[pbase + 1], p1);
        atomicAdd(&d_poolsum[pbase + 2], p2);
        atomicAdd(&d_poolsum[pbase + 3], p3);
        if (l == 0) atomicAdd(&d_gcnt[g], 1);
    }
}

// ---------------- 7. final MLP + log_softmax ----------------
__global__ void final_kernel(const float* __restrict__ lin_W, const float* __restrict__ lin_b,
                             const float* __restrict__ fc_W, const float* __restrict__ fc_b,
                             float* __restrict__ out) {
    int g = blockIdx.x, t = threadIdx.x;   // 64 threads
    __shared__ float pooled[256];
    __shared__ float hid[64];
    __shared__ float logits[CC];
    __shared__ float mx, lse;
    float cm = fmaxf((float)d_gcnt[g], 1.f);
    for (int j = t; j < 128; j += 64) {
        pooled[j] = __int_as_float(d_poolmax[g * 128 + j]);
        pooled[128 + j] = d_poolsum[g * 128 + j] / cm;
    }
    __syncthreads();
    float hs = lin_b[t];
    #pragma unroll 4
    for (int k = 0; k < 256; k++) hs = fmaf(pooled[k], lin_W[k * 64 + t], hs);
    hid[t] = frelu(hs);
    __syncthreads();
    if (t < CC) {
        float s = fc_b[t];
        #pragma unroll
        for (int h = 0; h < 64; h++) s = fmaf(hid[h], fc_W[h * CC + t], s);
        logits[t] = s;
    }
    __syncthreads();
    if (t == 0) {
        float m = logits[0];
        #pragma unroll
        for (int c = 1; c < CC; c++) m = fmaxf(m, logits[c]);
        float sum = 0.f;
        #pragma unroll
        for (int c = 0; c < CC; c++) sum += expf(logits[c] - m);
        mx = m; lse = logf(sum);
    }
    __syncthreads();
    if (t < CC) out[g * CC + t] = logits[t] - mx - lse;
}

// ---------------- launch ----------------
extern "C" void kernel_launch(void* const* d_in, const int* in_sizes, int n_in,
                              void* d_out, int out_size) {
    const float* x           = (const float*)d_in[0];
    const int*   edge_index  = (const int*)d_in[1];
    const int*   edge_type   = (const int*)d_in[2];
    const int*   graph_batch = (const int*)d_in[3];
    const float* film_lin_W  = (const float*)d_in[4];
    const float* film_film_W = (const float*)d_in[5];
    const float* film_film_b = (const float*)d_in[6];
    const float* skip_W      = (const float*)d_in[7];
    const float* skip_film_W = (const float*)d_in[8];
    const float* skip_film_b = (const float*)d_in[9];
    const float* gat_W       = (const float*)d_in[10];
    const float* gat_att_src = (const float*)d_in[11];
    const float* gat_att_dst = (const float*)d_in[12];
    const float* gat_b       = (const float*)d_in[13];
    const float* lin_W       = (const float*)d_in[14];
    const float* lin_b       = (const float*)d_in[15];
    const float* fc_W        = (const float*)d_in[16];
    const float* fc_b        = (const float*)d_in[17];
    float* out = (float*)d_out;

    int n = in_sizes[0] / FIN;     // 50000
    int ne = in_sizes[2];          // 800000

    pack_kernel<<<64, 256>>>(skip_film_W, skip_W, film_lin_W, film_film_W,
                             film_film_b, skip_film_b, gat_W);
    zero_kernel<<<256, 256>>>();

    // fork: sort chain on g_s2, GEMM chain on the main (capture) stream
    cudaEventRecord(g_evFork, 0);
    cudaStreamWaitEvent(g_s2, g_evFork, 0);

    hist_kernel<<<(ne + 255) / 256, 256, 0, g_s2>>>(ne, edge_index, edge_type);
    scan_local_kernel<<<SCAN_NB, SCAN_B, 0, g_s2>>>();
    scan_mid_kernel<<<1, 256, 0, g_s2>>>();
    scan_add_kernel<<<(NK + 255) / 256, 256, 0, g_s2>>>();
    scatter_kernel<<<(ne + 255) / 256, 256, 0, g_s2>>>(ne, edge_index, edge_type);
    cudaEventRecord(g_evJoin, g_s2);

    dim3 ggrid((n + 127) / 128, YW / 64);
    gemm_tc_kernel<<<ggrid, 256>>>(x, n);
    node_epi_kernel<<<(n * 8 + 255) / 256, 256>>>(n, gat_att_src, gat_att_dst);

    // join: agg needs both the sorted edges and Y
    cudaStreamWaitEvent(0, g_evJoin, 0);
    agg_kernel<<<(n + 7) / 8, 256>>>(n, graph_batch, gat_b);
    final_kernel<<<GG, 64>>>(lin_W, lin_b, fc_W, fc_b, out);
}

// round 15
// speedup vs baseline: 1.1520x; 1.1520x over previous
#include <cuda_runtime.h>
#include <cuda_bf16.h>
#include <cuda_fp16.h>
#include <math.h>

// Problem constants (fixed shapes per reference)
#define NN 50000
#define EE 800000
#define GG 64
#define FIN 64
#define HH 64
#define RR 3
#define CC 10
#define YW 832   // packed GEMM width
#define YH 640   // half-precision edge-accessed width (cols 192..832)
#define NK (NN * RR)                            // 150000 (dst,type) bins
#define SCAN_B 1024
#define SCAN_NB ((NK + SCAN_B - 1) / SCAN_B)    // 147

// Column layout in Wcat (GEMM output):
//  [0,128)   fs   = x @ skip_film_W + skip_film_b     -> d_Y192 fp32
//  [128,192) skip = x @ skip_W                        -> d_Y192 fp32
//  [192,384) xr   : r*64 + h  = x @ film_lin_W[r]     -> d_Yh fp16 (col j-192)
//  [384,768) fm   : r*128 + c (beta c<64, gamma c>=64)-> d_Yh fp16
//  [768,832) xp   = x @ gat_W                         -> d_Yh fp16 (cols 576..640)

// ---------------- scratch (device globals; no allocation allowed) -------------
__device__ float    d_Y192[(size_t)NN * 192];
__device__ __half   d_Yh[(size_t)NN * YH];
__device__ float    d_Wcat[64 * YW];
__device__ float    d_bcat[YW];
__device__ float    d_as[NN];
__device__ float    d_ad[NN];
__device__ int      d_hist[NK];
__device__ int      d_segoff[NK + 1];
__device__ int      d_cursor[NK];
__device__ int      d_blksum[SCAN_NB];
__device__ int      d_blkoff[SCAN_NB];
__device__ int      d_sorted[EE];          // src index (sorted by dst*3+type)
__device__ int      d_poolmax[GG * 128];   // float bits, values >= 0
__device__ float    d_poolsum[GG * 128];
__device__ int      d_gcnt[GG];

// ---------------- streams/events for fork-join inside graph capture -----------
static cudaStream_t g_s2;
static cudaEvent_t  g_evFork, g_evJoin;
struct _StreamInit {
    _StreamInit() {
        cudaStreamCreateWithFlags(&g_s2, cudaStreamNonBlocking);
        cudaEventCreateWithFlags(&g_evFork, cudaEventDisableTiming);
        cudaEventCreateWithFlags(&g_evJoin, cudaEventDisableTiming);
    }
};
static _StreamInit g_streamInit;

// ---------------- helpers ----------------
__device__ __forceinline__ float lrelu(float x) { return x > 0.f ? x : 0.2f * x; }
__device__ __forceinline__ float frelu(float x) { return fmaxf(x, 0.f); }
__device__ __forceinline__ unsigned f2tf(float f) {
    unsigned u;
    asm("cvt.rna.tf32.f32 %0, %1;" : "=r"(u) : "f"(f));
    return u;
}
__device__ __forceinline__ void mma_tf32(float* d, const unsigned* a, const unsigned* b) {
    asm volatile(
        "mma.sync.aligned.m16n8k8.row.col.f32.tf32.tf32.f32 "
        "{%0,%1,%2,%3}, {%4,%5,%6,%7}, {%8,%9}, {%0,%1,%2,%3};"
        : "+f"(d[0]), "+f"(d[1]), "+f"(d[2]), "+f"(d[3])
        : "r"(a[0]), "r"(a[1]), "r"(a[2]), "r"(a[3]), "r"(b[0]), "r"(b[1]));
}
__device__ __forceinline__ float2 ldh2(const __half* p) {
    return __half22float2(*(const __half2*)p);
}
__device__ __forceinline__ float4 ldh4(const __half* p) {
    uint2 u = *(const uint2*)p;
    __half2 a = *(__half2*)&u.x, b = *(__half2*)&u.y;
    float2 fa = __half22float2(a), fb = __half22float2(b);
    return make_float4(fa.x, fa.y, fb.x, fb.y);
}

// ---------------- 1. pack weights + biases ----------------
__global__ void pack_kernel(const float* __restrict__ skip_film_W,
                            const float* __restrict__ skip_W,
                            const float* __restrict__ film_lin_W,
                            const float* __restrict__ film_film_W,
                            const float* __restrict__ film_film_b,
                            const float* __restrict__ skip_film_b,
                            const float* __restrict__ gat_W) {
    int stride = blockDim.x * gridDim.x;
    for (int idx = blockIdx.x * blockDim.x + threadIdx.x; idx < 64 * YW; idx += stride) {
        int d = idx / YW, j = idx % YW;
        float v;
        if (j < 128)        v = skip_film_W[d * 128 + j];
        else if (j < 192)   v = skip_W[d * 64 + (j - 128)];
        else if (j < 384) { int r = (j - 192) >> 6, h = (j - 192) & 63;
                            v = film_lin_W[r * 4096 + d * 64 + h]; }
        else if (j < 768) { int r = (j - 384) >> 7, c = (j - 384) & 127;
                            v = film_film_W[r * 8192 + d * 128 + c]; }
        else                v = gat_W[d * 64 + (j - 768)];
        d_Wcat[idx] = v;
    }
    for (int j = blockIdx.x * blockDim.x + threadIdx.x; j < YW; j += stride) {
        float b = 0.f;
        if (j < 128)                 b = skip_film_b[j];
        else if (j >= 384 && j < 768) { int r = (j - 384) >> 7, c = (j - 384) & 127;
                                        b = film_film_b[r * 128 + c]; }
        d_bcat[j] = b;
    }
}

// ---------------- 2. zero scratch ----------------
__global__ void zero_kernel() {
    int stride = blockDim.x * gridDim.x;
    int t = blockIdx.x * blockDim.x + threadIdx.x;
    for (int i = t; i < NK; i += stride) { d_hist[i] = 0; d_cursor[i] = 0; }
    for (int i = t; i < GG * 128; i += stride) { d_poolmax[i] = 0; d_poolsum[i] = 0.f; }
    for (int i = t; i < GG; i += stride)      d_gcnt[i] = 0;
}

// ---------------- 3. tensor-core GEMM (TF32; 3x split only for fp32 cols) -----
__global__ __launch_bounds__(256) void gemm_tc_kernel(const float* __restrict__ A, int n) {
    __shared__ float As[128][68];
    __shared__ float Bs[64][72];
    int row0 = blockIdx.x * 128;
    int col0 = blockIdx.y * 64;
    int tid = threadIdx.x;
    bool is_half = (col0 >= 192);   // fp16-dest cols: single-pass TF32 suffices

    #pragma unroll
    for (int i = 0; i < 8; i++) {
        int e = i * 256 + tid;
        int r = e >> 4;
        int c4 = (e & 15) << 2;
        float4 v = make_float4(0.f, 0.f, 0.f, 0.f);
        if (row0 + r < n) v = *(const float4*)(A + (size_t)(row0 + r) * 64 + c4);
        As[r][c4] = v.x; As[r][c4 + 1] = v.y; As[r][c4 + 2] = v.z; As[r][c4 + 3] = v.w;
    }
    #pragma unroll
    for (int i = 0; i < 4; i++) {
        int e = i * 256 + tid;
        int k = e >> 4;
        int c4 = (e & 15) << 2;
        float4 v = *(const float4*)(d_Wcat + k * YW + col0 + c4);
        Bs[k][c4] = v.x; Bs[k][c4 + 1] = v.y; Bs[k][c4 + 2] = v.z; Bs[k][c4 + 3] = v.w;
    }
    __syncthreads();

    int warp = tid >> 5, lane = tid & 31;
    int wm = (warp >> 1) * 32;
    int wn = (warp & 1) * 32;
    int lr = lane >> 2;
    int lc = lane & 3;

    float acc[2][4][4] = {};
    #pragma unroll
    for (int k0 = 0; k0 < 64; k0 += 8) {
        unsigned abig[2][4], asml[2][4];
        float aval[2][4];
        #pragma unroll
        for (int mi = 0; mi < 2; mi++) {
            int r = wm + mi * 16 + lr;
            aval[mi][0] = As[r][k0 + lc];
            aval[mi][1] = As[r + 8][k0 + lc];
            aval[mi][2] = As[r][k0 + 4 + lc];
            aval[mi][3] = As[r + 8][k0 + 4 + lc];
            #pragma unroll
            for (int q = 0; q < 4; q++) abig[mi][q] = f2tf(aval[mi][q]);
        }
        unsigned bbig[4][2], bsml[4][2];
        float bval[4][2];
        #pragma unroll
        for (int ni = 0; ni < 4; ni++) {
            int c = wn + ni * 8 + lr;
            bval[ni][0] = Bs[k0 + lc][c];
            bval[ni][1] = Bs[k0 + 4 + lc][c];
            bbig[ni][0] = f2tf(bval[ni][0]);
            bbig[ni][1] = f2tf(bval[ni][1]);
        }
        #pragma unroll
        for (int mi = 0; mi < 2; mi++)
            #pragma unroll
            for (int ni = 0; ni < 4; ni++)
                mma_tf32(acc[mi][ni], abig[mi], bbig[ni]);
        if (!is_half) {   // correction passes only for fp32-dest columns
            #pragma unroll
            for (int mi = 0; mi < 2; mi++)
                #pragma unroll
                for (int q = 0; q < 4; q++)
                    asml[mi][q] = f2tf(aval[mi][q] - __uint_as_float(abig[mi][q]));
            #pragma unroll
            for (int ni = 0; ni < 4; ni++) {
                bsml[ni][0] = f2tf(bval[ni][0] - __uint_as_float(bbig[ni][0]));
                bsml[ni][1] = f2tf(bval[ni][1] - __uint_as_float(bbig[ni][1]));
            }
            #pragma unroll
            for (int mi = 0; mi < 2; mi++)
                #pragma unroll
                for (int ni = 0; ni < 4; ni++) {
                    mma_tf32(acc[mi][ni], abig[mi], bsml[ni]);
                    mma_tf32(acc[mi][ni], asml[mi], bbig[ni]);
                }
        }
    }

    #pragma unroll
    for (int mi = 0; mi < 2; mi++) {
        #pragma unroll
        for (int ni = 0; ni < 4; ni++) {
            int c = col0 + wn + ni * 8 + 2 * lc;
            float b0 = d_bcat[c], b1 = d_bcat[c + 1];
            int r0 = row0 + wm + mi * 16 + lr;
            #pragma unroll
            for (int rr = 0; rr < 2; rr++) {
                int r = r0 + rr * 8;
                if (r >= n) continue;
                float v0 = acc[mi][ni][rr * 2] + b0;
                float v1 = acc[mi][ni][rr * 2 + 1] + b1;
                if (is_half) {
                    *(__half2*)(d_Yh + (size_t)r * YH + (c - 192)) = __floats2half2_rn(v0, v1);
                } else {
                    *(float2*)(d_Y192 + (size_t)r * 192 + c) = make_float2(v0, v1);
                }
            }
        }
    }
}

// ---------------- 4. node epilogue: attention dot products --------------------
// 8 lanes per node, 16B loads, width-8 shuffle reduce.
__global__ void node_epi_kernel(int n, const float* __restrict__ att_src,
                                const float* __restrict__ att_dst) {
    int gt = blockIdx.x * blockDim.x + threadIdx.x;
    int node = gt >> 3;
    int sub = gt & 7;
    if (node >= n) return;
    const __half* xph = d_Yh + (size_t)node * YH + 576 + sub * 8;
    float4 a = ldh4(xph);
    float4 b = ldh4(xph + 4);
    int j = sub * 8;
    float ps = a.x * att_src[j]     + a.y * att_src[j + 1]
             + a.z * att_src[j + 2] + a.w * att_src[j + 3]
             + b.x * att_src[j + 4] + b.y * att_src[j + 5]
             + b.z * att_src[j + 6] + b.w * att_src[j + 7];
    float pd = a.x * att_dst[j]     + a.y * att_dst[j + 1]
             + a.z * att_dst[j + 2] + a.w * att_dst[j + 3]
             + b.x * att_dst[j + 4] + b.y * att_dst[j + 5]
             + b.z * att_dst[j + 6] + b.w * att_dst[j + 7];
    #pragma unroll
    for (int off = 4; off > 0; off >>= 1) {
        ps += __shfl_down_sync(0xffffffffu, ps, off, 8);
        pd += __shfl_down_sync(0xffffffffu, pd, off, 8);
    }
    if (sub == 0) { d_as[node] = ps; d_ad[node] = pd; }
}

// ---------------- 5. counting sort of edges by (dst,type) --------------------
__global__ void hist_kernel(int ne, const int* __restrict__ ei,
                            const int* __restrict__ et) {
    int e = blockIdx.x * blockDim.x + threadIdx.x;
    if (e >= ne) return;
    atomicAdd(&d_hist[ei[ne + e] * RR + et[e]], 1);
}

__global__ __launch_bounds__(SCAN_B) void scan_local_kernel() {
    __shared__ int warp_tot[32];
    int b = blockIdx.x, tid = threadIdx.x, lane = tid & 31, wid = tid >> 5;
    int i = b * SCAN_B + tid;
    int v = (i < NK) ? d_hist[i] : 0;
    int x = v;
    #pragma unroll
    for (int o = 1; o < 32; o <<= 1) {
        int y = __shfl_up_sync(0xffffffffu, x, o);
        if (lane >= o) x += y;
    }
    if (lane == 31) warp_tot[wid] = x;
    __syncthreads();
    if (wid == 0) {
        int w = warp_tot[lane];
        #pragma unroll
        for (int o = 1; o < 32; o <<= 1) {
            int y = __shfl_up_sync(0xffffffffu, w, o);
            if (lane >= o) w += y;
        }
        warp_tot[lane] = w;
    }
    __syncthreads();
    int incl = x + (wid > 0 ? warp_tot[wid - 1] : 0);
    if (i < NK) d_segoff[i] = incl - v;
    if (tid == SCAN_B - 1) d_blksum[b] = incl;
}

// scan the SCAN_NB (=147) block sums with one 256-thread block
__global__ void scan_mid_kernel() {
    __shared__ int wt[8];
    int tid = threadIdx.x, lane = tid & 31, wid = tid >> 5;
    int v = (tid < SCAN_NB) ? d_blksum[tid] : 0;
    int x = v;
    #pragma unroll
    for (int o = 1; o < 32; o <<= 1) {
        int y = __shfl_up_sync(0xffffffffu, x, o);
        if (lane >= o) x += y;
    }
    if (lane == 31) wt[wid] = x;
    __syncthreads();
    if (wid == 0) {
        int w = (lane < 8) ? wt[lane] : 0;
        #pragma unroll
        for (int o = 1; o < 8; o <<= 1) {
            int y = __shfl_up_sync(0xffffffffu, w, o);
            if (lane >= o) w += y;
        }
        if (lane < 8) wt[lane] = w;
    }
    __syncthreads();
    int incl = x + (wid > 0 ? wt[wid - 1] : 0);
    if (tid < SCAN_NB) d_blkoff[tid] = incl - v;
    if (tid == 0) d_segoff[NK] = wt[7];
}

__global__ void scan_add_kernel() {
    int i = blockIdx.x * blockDim.x + threadIdx.x;
    if (i < NK) d_segoff[i] += d_blkoff[i >> 10];
}

__global__ void scatter_kernel(int ne, const int* __restrict__ ei,
                               const int* __restrict__ et) {
    int e = blockIdx.x * blockDim.x + threadIdx.x;
    if (e >= ne) return;
    int s = ei[e];
    int k = ei[ne + e] * RR + et[e];
    int pos = d_segoff[k] + atomicAdd(&d_cursor[k], 1);
    d_sorted[pos] = s;
}

// ---------------- 6. aggregation + pooling: one warp per dst ------------------
// R12 shape (branchless per-type subsegments, uniform lanes, ldh2 both rows)
// + software-pipelined batch loads: prefetch next batch's d_sorted/d_as gathers
// while the broadcast loop processes the current batch. Pooling staged in smem
// per block (graph_batch is sorted).
__global__ __launch_bounds__(256) void agg_kernel(int n, const int* __restrict__ gb,
                                                  const float* __restrict__ gat_b) {
    __shared__ int   s_g[8];
    __shared__ int   s_max[128];
    __shared__ float s_sum[128];
    int wslot = threadIdx.x >> 5;
    int l = threadIdx.x & 31;
    int d = blockIdx.x * 8 + wslot;
    bool active = d < n;

    float v1x = 0.f, v1y = 0.f, v2x = 0.f, v2y = 0.f;
    int g = -1;

    if (active) {
        const __half* yh_d = d_Yh + (size_t)d * YH;
        float ad_d = d_ad[d];
        float gx = 0.f, gy = 0.f, denom = 0.f;
        float filmx = 0.f, filmy = 0.f;

        #pragma unroll
        for (int t = 0; t < RR; t++) {
            float2 be = ldh2(yh_d + 192 + t * 128 + 2 * l);
            float2 ga = ldh2(yh_d + 192 + t * 128 + 64 + 2 * l);
            int beg = d_segoff[d * RR + t], end = d_segoff[d * RR + t + 1];
            float fx = 0.f, fy = 0.f;

            // prologue: load first batch
            int i0 = beg + l;
            int sk = 0; float asv = 0.f;
            if (i0 < end) { sk = d_sorted[i0]; asv = d_as[sk]; }

            for (int base = beg; base < end; base += 32) {
                // prefetch next batch (independent of current broadcast loop)
                int i2 = base + 32 + l;
                int sk2 = 0; float as2 = 0.f;
                if (i2 < end) { sk2 = d_sorted[i2]; as2 = d_as[sk2]; }

                float ex = __expf(lrelu(asv + ad_d));
                if (base + l >= end) ex = 0.f;
                int m = min(32, end - base);
                #pragma unroll 4
                for (int j = 0; j < m; j++) {
                    int sj    = __shfl_sync(0xffffffffu, sk, j);
                    float exj = __shfl_sync(0xffffffffu, ex, j);
                    denom += exj;
                    const __half* yh_s = d_Yh + (size_t)sj * YH;
                    float2 xp = ldh2(yh_s + 576 + 2 * l);
                    gx += exj * xp.x; gy += exj * xp.y;
                    float2 xr = ldh2(yh_s + t * 64 + 2 * l);
                    fx += frelu(ga.x * xr.x + be.x);
                    fy += frelu(ga.y * xr.y + be.y);
                }
                sk = sk2; asv = as2;
            }
            float rc = 1.f / fmaxf((float)(end - beg), 1.f);
            filmx += fx * rc;
            filmy += fy * rc;
        }

        // GAT self loop
        float ex_self = __expf(lrelu(d_as[d] + ad_d));
        denom += ex_self;
        float2 xp_d = ldh2(yh_d + 576 + 2 * l);
        gx += ex_self * xp_d.x; gy += ex_self * xp_d.y;
        float rden = 1.f / denom;

        const float* yr = d_Y192 + (size_t)d * 192;
        float2 fsb = *(const float2*)(yr + 2 * l);
        float2 fsg = *(const float2*)(yr + 64 + 2 * l);
        float2 skv = *(const float2*)(yr + 128 + 2 * l);
        v1x = frelu(frelu(fsg.x * skv.x + fsb.x) + filmx);
        v1y = frelu(frelu(fsg.y * skv.y + fsb.y) + filmy);

        v2x = frelu(gx * rden + gat_b[2 * l]);
        v2y = frelu(gy * rden + gat_b[2 * l + 1]);

        g = __shfl_sync(0xffffffffu, (l == 0) ? gb[d] : 0, 0);
    }

    if (l == 0) s_g[wslot] = active ? g : -1;
    __syncthreads();
    int g0 = s_g[0];
    bool uni = (g0 >= 0);
    #pragma unroll
    for (int i = 1; i < 8; i++) uni = uni && (s_g[i] == g0);

    if (uni) {
        // block-staged pooling: smem reduce, then 128+128 global atomics per block
        if (threadIdx.x < 128) { s_max[threadIdx.x] = 0; s_sum[threadIdx.x] = 0.f; }
        __syncthreads();
        atomicMax(&s_max[2 * l],      __float_as_int(v1x));
        atomicMax(&s_max[2 * l + 1],  __float_as_int(v1y));
        atomicMax(&s_max[64 + 2 * l], __float_as_int(v2x));
        atomicMax(&s_max[65 + 2 * l], __float_as_int(v2y));
        atomicAdd(&s_sum[2 * l],      v1x);
        atomicAdd(&s_sum[2 * l + 1],  v1y);
        atomicAdd(&s_sum[64 + 2 * l], v2x);
        atomicAdd(&s_sum[65 + 2 * l], v2y);
        __syncthreads();
        if (threadIdx.x < 128) {
            atomicMax(&d_poolmax[g0 * 128 + threadIdx.x], s_max[threadIdx.x]);
            atomicAdd(&d_poolsum[g0 * 128 + threadIdx.x], s_sum[threadIdx.x]);
        }
        if (threadIdx.x == 0) atomicAdd(&d_gcnt[g0], 8);
    } else if (active) {
        // fallback: direct global atomics (graph-boundary or tail blocks)
        int pbase = g * 128 + 2 * l;
        atomicMax(&d_poolmax[pbase],      __float_as_int(v1x));
        atomicMax(&d_poolmax[pbase + 1],  __float_as_int(v1y));
        atomicMax(&d_poolmax[pbase + 64], __float_as_int(v2x));
        atomicMax(&d_poolmax[pbase + 65], __float_as_int(v2y));
        atomicAdd(&d_poolsum[pbase],      v1x);
        atomicAdd(&d_poolsum[pbase + 1],  v1y);
        atomicAdd(&d_poolsum[pbase + 64], v2x);
        atomicAdd(&d_poolsum[pbase + 65], v2y);
        if (l == 0) atomicAdd(&d_gcnt[g], 1);
    }
}

// ---------------- 7. final MLP + log_softmax ----------------
__global__ void final_kernel(const float* __restrict__ lin_W, const float* __restrict__ lin_b,
                             const float* __restrict__ fc_W, const float* __restrict__ fc_b,
                             float* __restrict__ out) {
    int g = blockIdx.x, t = threadIdx.x;   // 64 threads
    __shared__ float pooled[256];
    __shared__ float hid[64];
    __shared__ float logits[CC];
    __shared__ float mx, lse;
    float cm = fmaxf((float)d_gcnt[g], 1.f);
    for (int j = t; j < 128; j += 64) {
        pooled[j] = __int_as_float(d_poolmax[g * 128 + j]);
        pooled[128 + j] = d_poolsum[g * 128 + j] / cm;
    }
    __syncthreads();
    float hs = lin_b[t];
    #pragma unroll 4
    for (int k = 0; k < 256; k++) hs = fmaf(pooled[k], lin_W[k * 64 + t], hs);
    hid[t] = frelu(hs);
    __syncthreads();
    if (t < CC) {
        float s = fc_b[t];
        #pragma unroll
        for (int h = 0; h < 64; h++) s = fmaf(hid[h], fc_W[h * CC + t], s);
        logits[t] = s;
    }
    __syncthreads();
    if (t == 0) {
        float m = logits[0];
        #pragma unroll
        for (int c = 1; c < CC; c++) m = fmaxf(m, logits[c]);
        float sum = 0.f;
        #pragma unroll
        for (int c = 0; c < CC; c++) sum += expf(logits[c] - m);
        mx = m; lse = logf(sum);
    }
    __syncthreads();
    if (t < CC) out[g * CC + t] = logits[t] - mx - lse;
}

// ---------------- launch ----------------
extern "C" void kernel_launch(void* const* d_in, const int* in_sizes, int n_in,
                              void* d_out, int out_size) {
    const float* x           = (const float*)d_in[0];
    const int*   edge_index  = (const int*)d_in[1];
    const int*   edge_type   = (const int*)d_in[2];
    const int*   graph_batch = (const int*)d_in[3];
    const float* film_lin_W  = (const float*)d_in[4];
    const float* film_film_W = (const float*)d_in[5];
    const float* film_film_b = (const float*)d_in[6];
    const float* skip_W      = (const float*)d_in[7];
    const float* skip_film_W = (const float*)d_in[8];
    const float* skip_film_b = (const float*)d_in[9];
    const float* gat_W       = (const float*)d_in[10];
    const float* gat_att_src = (const float*)d_in[11];
    const float* gat_att_dst = (const float*)d_in[12];
    const float* gat_b       = (const float*)d_in[13];
    const float* lin_W       = (const float*)d_in[14];
    const float* lin_b       = (const float*)d_in[15];
    const float* fc_W        = (const float*)d_in[16];
    const float* fc_b        = (const float*)d_in[17];
    float* out = (float*)d_out;

    int n = in_sizes[0] / FIN;     // 50000
    int ne = in_sizes[2];          // 800000

    pack_kernel<<<64, 256>>>(skip_film_W, skip_W, film_lin_W, film_film_W,
                             film_film_b, skip_film_b, gat_W);
    zero_kernel<<<256, 256>>>();

    // fork: sort chain on g_s2, GEMM chain on the main (capture) stream
    cudaEventRecord(g_evFork, 0);
    cudaStreamWaitEvent(g_s2, g_evFork, 0);

    hist_kernel<<<(ne + 255) / 256, 256, 0, g_s2>>>(ne, edge_index, edge_type);
    scan_local_kernel<<<SCAN_NB, SCAN_B, 0, g_s2>>>();
    scan_mid_kernel<<<1, 256, 0, g_s2>>>();
    scan_add_kernel<<<(NK + 255) / 256, 256, 0, g_s2>>>();
    scatter_kernel<<<(ne + 255) / 256, 256, 0, g_s2>>>(ne, edge_index, edge_type);
    cudaEventRecord(g_evJoin, g_s2);

    dim3 ggrid((n + 127) / 128, YW / 64);
    gemm_tc_kernel<<<ggrid, 256>>>(x, n);
    node_epi_kernel<<<(n * 8 + 255) / 256, 256>>>(n, gat_att_src, gat_att_dst);

    // join: agg needs both the sorted edges and Y
    cudaStreamWaitEvent(0, g_evJoin, 0);
    agg_kernel<<<(n + 7) / 8, 256>>>(n, graph_batch, gat_b);
    final_kernel<<<GG, 64>>>(lin_W, lin_b, fc_W, fc_b, out);
}